// round 17
// baseline (speedup 1.0000x reference)
#include <cuda_runtime.h>
#include <cuda_fp16.h>
#include <math.h>
#include <stdint.h>

// ---------------- scratch (allocation-free: __device__ globals) ----------------
__device__ __align__(1024) uint32_t g_xs_big[32768ULL * 64];
__device__ __align__(1024) uint32_t g_xs_sml[32768ULL * 64];
__device__ __align__(1024) uint32_t g_h_big[32768ULL * 256];
__device__ __align__(1024) uint32_t g_h_sml[32768ULL * 256];
__device__ __align__(1024) uint32_t g_w0b[2][512 * 64];
__device__ __align__(1024) uint32_t g_w0s[2][512 * 64];
__device__ __align__(1024) uint32_t g_w1b[2][1792 * 256];
__device__ __align__(1024) uint32_t g_w1s[2][1792 * 256];
__device__ __align__(1024) float    g_ldp[2][32768ULL * 16];

#define BVAL   3.0f
#define KBINS  5
#define MIN_BW 0.001f
#define MIN_BH 0.001f
#define MIN_DV 0.001f

// ======================= helpers =======================
__device__ __forceinline__ int gidx(int kpg) {
    return (kpg & ~15) | ((kpg & 3) << 2) | ((kpg >> 2) & 3);
}

__device__ __forceinline__ void split2h(float x0, float x1, uint32_t& b, uint32_t& s) {
    __half b0 = __float2half_rn(x0);
    __half b1 = __float2half_rn(x1);
    float r0 = x0 - __half2float(b0);
    float r1 = x1 - __half2float(b1);
    __half s0 = __float2half_rn(r0);
    __half s1 = __float2half_rn(r1);
    b = (uint32_t)__half_as_ushort(b0) | ((uint32_t)__half_as_ushort(b1) << 16);
    s = (uint32_t)__half_as_ushort(s0) | ((uint32_t)__half_as_ushort(s1) << 16);
}

__device__ __forceinline__ void mma_h(float* d,
                                      uint32_t a0, uint32_t a1, uint32_t a2, uint32_t a3,
                                      uint32_t b0, uint32_t b1) {
    asm volatile(
        "mma.sync.aligned.m16n8k16.row.col.f32.f16.f16.f32 "
        "{%0,%1,%2,%3}, {%4,%5,%6,%7}, {%8,%9}, {%0,%1,%2,%3};"
        : "+f"(d[0]), "+f"(d[1]), "+f"(d[2]), "+f"(d[3])
        : "r"(a0), "r"(a1), "r"(a2), "r"(a3), "r"(b0), "r"(b1));
}

#define CP16(dst, src) \
    asm volatile("cp.async.cg.shared.global [%0], [%1], 16;" :: "r"(dst), "l"(src) : "memory")
#define CP_COMMIT() asm volatile("cp.async.commit_group;" ::: "memory")
#define CP_WAIT1()  asm volatile("cp.async.wait_group 1;" ::: "memory")
#define CP_WAIT0()  asm volatile("cp.async.wait_group 0;" ::: "memory")

__device__ __forceinline__ uint32_t smem_u32(const void* p) {
    uint32_t a;
    asm("{ .reg .u64 t; cvta.to.shared.u64 t, %1; cvt.u32.u64 %0, t; }" : "=r"(a) : "l"(p));
    return a;
}

__device__ __forceinline__ float fexpf(float x) { return __expf(x); }
__device__ __forceinline__ float flogf(float x) { return __logf(x); }
__device__ __forceinline__ float fsoftplus(float x) {
    return (x > 20.0f) ? x : __logf(1.0f + __expf(x));
}

// rational-quadratic spline (identical arithmetic to rounds 15/16)
__device__ __forceinline__ float spline_eval(const float* raw, float t, float* ldOut) {
    float cw[6], wd[5];
    {
        float m = raw[0];
#pragma unroll
        for (int j = 1; j < 5; j++) m = fmaxf(m, raw[j]);
        float e[5], s = 0.f;
#pragma unroll
        for (int j = 0; j < 5; j++) { e[j] = fexpf(raw[j] - m); s += e[j]; }
        float inv = __fdividef(1.0f, s);
        float Wu[5];
#pragma unroll
        for (int j = 0; j < 5; j++) Wu[j] = 2.0f * BVAL * e[j] * inv;
        float m2 = Wu[0];
#pragma unroll
        for (int j = 1; j < 5; j++) m2 = fmaxf(m2, Wu[j]);
        float e2[5], s2 = 0.f;
#pragma unroll
        for (int j = 0; j < 5; j++) { e2[j] = fexpf(Wu[j] - m2); s2 += e2[j]; }
        float inv2 = __fdividef(1.0f, s2);
        cw[0] = -BVAL;
        float run = 0.f;
#pragma unroll
        for (int j = 0; j < 5; j++) {
            float w = MIN_BW + (1.0f - MIN_BW * KBINS) * (e2[j] * inv2);
            run += w;
            cw[j + 1] = 2.0f * BVAL * run - BVAL;
        }
        cw[5] = BVAL;
#pragma unroll
        for (int j = 0; j < 5; j++) wd[j] = cw[j + 1] - cw[j];
    }
    float ch[6], hd[5];
    {
        float m = raw[5];
#pragma unroll
        for (int j = 1; j < 5; j++) m = fmaxf(m, raw[5 + j]);
        float e[5], s = 0.f;
#pragma unroll
        for (int j = 0; j < 5; j++) { e[j] = fexpf(raw[5 + j] - m); s += e[j]; }
        float inv = __fdividef(1.0f, s);
        float Hu[5];
#pragma unroll
        for (int j = 0; j < 5; j++) Hu[j] = 2.0f * BVAL * e[j] * inv;
        float m2 = Hu[0];
#pragma unroll
        for (int j = 1; j < 5; j++) m2 = fmaxf(m2, Hu[j]);
        float e2[5], s2 = 0.f;
#pragma unroll
        for (int j = 0; j < 5; j++) { e2[j] = fexpf(Hu[j] - m2); s2 += e2[j]; }
        float inv2 = __fdividef(1.0f, s2);
        ch[0] = -BVAL;
        float run = 0.f;
#pragma unroll
        for (int j = 0; j < 5; j++) {
            float h = MIN_BH + (1.0f - MIN_BH * KBINS) * (e2[j] * inv2);
            run += h;
            ch[j + 1] = 2.0f * BVAL * run - BVAL;
        }
        ch[5] = BVAL;
#pragma unroll
        for (int j = 0; j < 5; j++) hd[j] = ch[j + 1] - ch[j];
    }
    float deriv[6];
    deriv[0] = 1.0f;
    deriv[5] = 1.0f;
#pragma unroll
    for (int j = 0; j < 4; j++) {
        float du = fsoftplus(raw[10 + j]);
        deriv[j + 1] = MIN_DV + fsoftplus(du);
    }
    const float xc = fminf(fmaxf(t, -BVAL), BVAL);
    int cnt = 0;
#pragma unroll
    for (int j = 0; j < 6; j++) cnt += (xc >= cw[j]) ? 1 : 0;
    int idx = min(max(cnt - 1, 0), 4);

    const float icw = cw[idx], iw = wd[idx];
    const float ich = ch[idx], ih = hd[idx];
    const float delta = __fdividef(ih, iw);
    const float dk = deriv[idx], dk1 = deriv[idx + 1];
    const float theta = __fdividef(xc - icw, iw);
    const float t1m = theta * (1.0f - theta);
    const float num = ih * (delta * theta * theta + dk * t1m);
    const float den = delta + (dk + dk1 - 2.0f * delta) * t1m;
    const float y = ich + __fdividef(num, den);
    const float omt = 1.0f - theta;
    const float dnum = delta * delta * (dk1 * theta * theta + 2.0f * delta * t1m + dk * omt * omt);
    const float ld = flogf(__fdividef(dnum, den * den));

    const bool inside = (t >= -BVAL) && (t <= BVAL);
    *ldOut = inside ? ld : 0.0f;
    return inside ? y : t;
}

// ======================= converters =======================
__device__ __forceinline__ void conv_w_body(
    const float* __restrict__ w, int M, int K2, int m0, int kp0,
    uint32_t* __restrict__ ob, uint32_t* __restrict__ os,
    uint32_t (*tb)[33], uint32_t (*ts)[33], int tid)
{
    const int xx = tid & 31, yy = tid >> 5;
    for (int i = yy; i < 32; i += 8) {
        int kpg = kp0 + i, m = m0 + xx;
        float v0 = w[(size_t)(2 * kpg) * M + m];
        float v1 = w[(size_t)(2 * kpg + 1) * M + m];
        split2h(v0, v1, tb[i][xx], ts[i][xx]);
    }
    __syncthreads();
    for (int i = yy; i < 32; i += 8) {
        int m = m0 + i;
        size_t dst = (size_t)m * K2 + gidx(kp0 + xx);
        ob[dst] = tb[xx][i]; os[dst] = ts[xx][i];
    }
}

__global__ void __launch_bounds__(256) conv_all(
    const float* __restrict__ x, int xoff,
    const float* __restrict__ w0a, const float* __restrict__ w1a,
    const float* __restrict__ w0c, const float* __restrict__ w1c,
    uint32_t* __restrict__ w0bD, uint32_t* __restrict__ w0sD,
    uint32_t* __restrict__ w1bD, uint32_t* __restrict__ w1sD,
    uint32_t* __restrict__ xb, uint32_t* __restrict__ xs)
{
    __shared__ uint32_t tb[32][33], ts[32][33];
    const int bid = blockIdx.x;
    const int tid = threadIdx.x;
    if (bid < 32) {
        conv_w_body(w0a, 512, 64, (bid & 15) * 32, (bid >> 4) * 32, w0bD, w0sD, tb, ts, tid);
    } else if (bid < 480) {
        int b = bid - 32;
        conv_w_body(w1a, 1792, 256, (b % 56) * 32, (b / 56) * 32, w1bD, w1sD, tb, ts, tid);
    } else if (bid < 512) {
        int b = bid - 480;
        conv_w_body(w0c, 512, 64, (b & 15) * 32, (b >> 4) * 32,
                    w0bD + 512 * 64, w0sD + 512 * 64, tb, ts, tid);
    } else if (bid < 960) {
        int b = bid - 512;
        conv_w_body(w1c, 1792, 256, (b % 56) * 32, (b / 56) * 32,
                    w1bD + 1792 * 256, w1sD + 1792 * 256, tb, ts, tid);
    } else {
        int t = (bid - 960) * 256 + tid;
        int row = t >> 6, kpg = t & 63;
        float2 v = *(const float2*)(x + (size_t)row * 256 + xoff + 2 * kpg);
        uint32_t b_, s_;
        split2h(v.x, v.y, b_, s_);
        int dst = row * 64 + gidx(kpg);
        xb[dst] = b_; xs[dst] = s_;
    }
}

// ======================= GEMM1: fp16 3-term, tile 128x64 =======================
// 256 threads, 8 warps (2m x 4n), warp tile 64x16. K2=64, 4 iters.
// Stage 24KB (Ab 8K | As 8K | Bb 4K | Bs 4K), 3 stages = 72KB.
// Grid (8, N/128) = 2048 blocks -> ~7 waves (kills the 3.5-wave tail of the
// old 128x128 shape). Epilogue: tanh -> smem float2 -> float4 writeout.
#define G1_SMEM (3 * 24576)

__global__ void __launch_bounds__(256, 2) gemm1_h3(
    const uint32_t* __restrict__ Ab, const uint32_t* __restrict__ As,
    const uint32_t* __restrict__ Bb, const uint32_t* __restrict__ Bs,
    const float* __restrict__ bias,
    uint32_t* __restrict__ Hb, uint32_t* __restrict__ Hs,
    int M, int K2)
{
    extern __shared__ uint32_t sm[];
    const uint32_t sbase = smem_u32(sm);
    const int tid  = threadIdx.x;
    const int lane = tid & 31;
    const int wid  = tid >> 5;
    const int warp_m = wid & 1;      // 64 rows
    const int warp_n = wid >> 1;     // 0..3, 16 cols each
    const int rowBase = blockIdx.y * 128;
    const int colBase = blockIdx.x * 64;
    const int q  = lane & 3;
    const int rw = lane >> 2;

    // A staging: 128 rows x 16 words/iter; thread -> row (tid>>1), 8-word half
    const int cr  = tid >> 1;
    const int cw8 = (tid & 1) * 8;
    const uint32_t* gAb = Ab + (size_t)(rowBase + cr) * K2 + cw8;
    const uint32_t* gAs = As + (size_t)(rowBase + cr) * K2 + cw8;
    const uint32_t sdA = sbase + (uint32_t)(cr * 16 + cw8) * 4;
    // B staging: 64 rows x 16 words/iter; thread -> row (tid>>2), 4-word piece
    const int cr2 = tid >> 2;
    const int cp2 = (tid & 3) * 4;
    const uint32_t* gBb = Bb + (size_t)(colBase + cr2) * K2 + cp2;
    const uint32_t* gBs = Bs + (size_t)(colBase + cr2) * K2 + cp2;
    const uint32_t sdB = sbase + (uint32_t)(4096 + cr2 * 16 + cp2) * 4;

#define STAGE1(it, buf) do { \
        uint32_t dA = sdA + (uint32_t)(buf) * 24576u; \
        uint32_t dB = sdB + (uint32_t)(buf) * 24576u; \
        CP16(dA,        gAb + (it) * 16); CP16(dA + 16,        gAb + (it) * 16 + 4); \
        CP16(dA + 8192, gAs + (it) * 16); CP16(dA + 8192 + 16, gAs + (it) * 16 + 4); \
        CP16(dB,        gBb + (it) * 16); \
        CP16(dB + 4096, gBs + (it) * 16); \
        CP_COMMIT(); \
    } while (0)

    float acc[4][2][4];
#pragma unroll
    for (int mt = 0; mt < 4; mt++)
#pragma unroll
        for (int nt = 0; nt < 2; nt++)
#pragma unroll
            for (int c = 0; c < 4; c++) acc[mt][nt][c] = 0.f;

    const int nIter = K2 >> 4;   // 4
    STAGE1(0, 0);
    STAGE1(1, 1);

    int buf = 0;
    for (int it = 0; it < nIter; it++) {
        if (it + 1 < nIter) { CP_WAIT1(); } else { CP_WAIT0(); }
        __syncthreads();
        if (it + 2 < nIter) {
            int nb = buf + 2; if (nb >= 3) nb -= 3;
            STAGE1(it + 2, nb);
        }
        const uint32_t* sA = sm + buf * 6144;
        const uint32_t* sB = sA + 4096;

        uint4 bb[2], bs[2];
#pragma unroll
        for (int nt = 0; nt < 2; nt++) {
            const uint32_t* p = sB + (warp_n * 16 + nt * 8 + rw) * 16 + 4 * q;
            bb[nt] = *(const uint4*)p;
            bs[nt] = *(const uint4*)(p + 1024);
        }
#pragma unroll
        for (int mt = 0; mt < 4; mt++) {
            const uint32_t* p = sA + (warp_m * 64 + mt * 16 + rw) * 16 + 4 * q;
            uint4 alo = *(const uint4*)p;
            uint4 ahi = *(const uint4*)(p + 128);
            uint4 slo = *(const uint4*)(p + 2048);
            uint4 shi = *(const uint4*)(p + 2048 + 128);
#pragma unroll
            for (int nt = 0; nt < 2; nt++)
                mma_h(acc[mt][nt], alo.x, ahi.x, alo.y, ahi.y, bb[nt].x, bb[nt].y);
#pragma unroll
            for (int nt = 0; nt < 2; nt++)
                mma_h(acc[mt][nt], alo.z, ahi.z, alo.w, ahi.w, bb[nt].z, bb[nt].w);
#pragma unroll
            for (int nt = 0; nt < 2; nt++)
                mma_h(acc[mt][nt], slo.x, shi.x, slo.y, shi.y, bb[nt].x, bb[nt].y);
#pragma unroll
            for (int nt = 0; nt < 2; nt++)
                mma_h(acc[mt][nt], slo.z, shi.z, slo.w, shi.w, bb[nt].z, bb[nt].w);
#pragma unroll
            for (int nt = 0; nt < 2; nt++)
                mma_h(acc[mt][nt], alo.x, ahi.x, alo.y, ahi.y, bs[nt].x, bs[nt].y);
#pragma unroll
            for (int nt = 0; nt < 2; nt++)
                mma_h(acc[mt][nt], alo.z, ahi.z, alo.w, ahi.w, bs[nt].z, bs[nt].w);
        }
        buf++; if (buf >= 3) buf -= 3;
    }

    // ---- epilogue: tanh -> smem (float2) -> split-fp16 float4 writeout ----
    __syncthreads();
    float* fs = (float*)sm;   // 128 x 64 fp32 = 32 KB
#pragma unroll
    for (int mt = 0; mt < 4; mt++) {
#pragma unroll
        for (int nt = 0; nt < 2; nt++) {
            int r = warp_m * 64 + mt * 16 + rw;
            int c = warp_n * 16 + nt * 8 + q * 2;
            float b0 = bias[colBase + c], b1 = bias[colBase + c + 1];
            *(float2*)&fs[r * 64 + c] =
                make_float2(tanhf(acc[mt][nt][0] + b0), tanhf(acc[mt][nt][1] + b1));
            *(float2*)&fs[(r + 8) * 64 + c] =
                make_float2(tanhf(acc[mt][nt][2] + b0), tanhf(acc[mt][nt][3] + b1));
        }
    }
    __syncthreads();
    const int pairBase = colBase >> 1;   // multiple of 32
    const int Mw = M >> 1;
#pragma unroll
    for (int i = 0; i < 8; i++) {
        int p = tid + i * 256;           // 0..2047 float4 groups
        int r = p >> 4;                  // 0..127
        int f4 = p & 15;                 // float4 index within row
        float4 v = *(const float4*)&fs[r * 64 + f4 * 4];
        int kp0 = f4 * 2;
        uint32_t b0, s0, b1, s1;
        split2h(v.x, v.y, b0, s0);
        split2h(v.z, v.w, b1, s1);
        size_t rowOff = (size_t)(rowBase + r) * Mw + pairBase;
        Hb[rowOff + gidx(kp0)]     = b0;
        Hs[rowOff + gidx(kp0)]     = s0;
        Hb[rowOff + gidx(kp0 + 1)] = b1;
        Hs[rowOff + gidx(kp0 + 1)] = s1;
    }
#undef STAGE1
}

// ======================= GEMM2 fused with spline (unchanged from round 16) =======================
#define G2_SMEM (3 * 24576)

__global__ void __launch_bounds__(256, 2) gemm2_fused(
    const uint32_t* __restrict__ Ab, const uint32_t* __restrict__ As,
    const uint32_t* __restrict__ Bb,
    const float* __restrict__ bias,
    const float* __restrict__ x, int xoff,
    float* __restrict__ z, int zoff,
    uint32_t* __restrict__ zb, uint32_t* __restrict__ zs,
    float* __restrict__ ldpart)
{
    extern __shared__ uint32_t sm[];
    const uint32_t sbase = smem_u32(sm);
    const int tid  = threadIdx.x;
    const int lane = tid & 31;
    const int wid  = tid >> 5;
    const int warp_m = wid & 3;
    const int warp_n = wid >> 2;
    const int bx = blockIdx.x;
    const int rowBase = blockIdx.y * 128;
    const int colBase = bx * 112;
    const int q  = lane & 3;
    const int rw = lane >> 2;
    const int K2 = 256;

    const int cr  = tid >> 1;
    const int cw8 = (tid & 1) * 8;
    const uint32_t* gAb = Ab + (size_t)(rowBase + cr) * K2 + cw8;
    const uint32_t* gAs = As + (size_t)(rowBase + cr) * K2 + cw8;
    const uint32_t* gBb = Bb + (size_t)(colBase + cr) * K2 + cw8;
    const uint32_t sdst = sbase + (uint32_t)(cr * 16 + cw8) * 4;
    const bool doB = (cr < 112);

#define STAGE2(it, buf) do { \
        uint32_t d0 = sdst + (uint32_t)(buf) * 24576u; \
        CP16(d0,          gAb + (it) * 16); CP16(d0 + 16,         gAb + (it) * 16 + 4); \
        CP16(d0 + 8192,   gAs + (it) * 16); CP16(d0 + 8192 + 16,  gAs + (it) * 16 + 4); \
        if (doB) { \
            CP16(d0 + 16384, gBb + (it) * 16); CP16(d0 + 16384 + 16, gBb + (it) * 16 + 4); \
        } \
        CP_COMMIT(); \
    } while (0)

    float acc[2][7][4];
#pragma unroll
    for (int mt = 0; mt < 2; mt++)
#pragma unroll
        for (int nt = 0; nt < 7; nt++)
#pragma unroll
            for (int c = 0; c < 4; c++) acc[mt][nt][c] = 0.f;

    const int nIter = 16;
    STAGE2(0, 0);
    STAGE2(1, 1);

    int buf = 0;
    for (int it = 0; it < nIter; it++) {
        if (it + 1 < nIter) { CP_WAIT1(); } else { CP_WAIT0(); }
        __syncthreads();
        if (it + 2 < nIter) {
            int nb = buf + 2; if (nb >= 3) nb -= 3;
            STAGE2(it + 2, nb);
        }
        const uint32_t* sA = sm + buf * 6144;
        const uint32_t* sB = sA + 4096;

        uint4 bb[7];
#pragma unroll
        for (int nt = 0; nt < 7; nt++) {
            const uint32_t* p = sB + (warp_n * 56 + nt * 8 + rw) * 16 + 4 * q;
            bb[nt] = *(const uint4*)p;
        }
#pragma unroll
        for (int mt = 0; mt < 2; mt++) {
            const uint32_t* p = sA + (warp_m * 32 + mt * 16 + rw) * 16 + 4 * q;
            uint4 alo = *(const uint4*)p;
            uint4 ahi = *(const uint4*)(p + 128);
            uint4 slo = *(const uint4*)(p + 2048);
            uint4 shi = *(const uint4*)(p + 2048 + 128);
#pragma unroll
            for (int nt = 0; nt < 7; nt++)
                mma_h(acc[mt][nt], alo.x, ahi.x, alo.y, ahi.y, bb[nt].x, bb[nt].y);
#pragma unroll
            for (int nt = 0; nt < 7; nt++)
                mma_h(acc[mt][nt], alo.z, ahi.z, alo.w, ahi.w, bb[nt].z, bb[nt].w);
#pragma unroll
            for (int nt = 0; nt < 7; nt++)
                mma_h(acc[mt][nt], slo.x, shi.x, slo.y, shi.y, bb[nt].x, bb[nt].y);
#pragma unroll
            for (int nt = 0; nt < 7; nt++)
                mma_h(acc[mt][nt], slo.z, shi.z, slo.w, shi.w, bb[nt].z, bb[nt].w);
        }
        buf++; if (buf >= 3) buf -= 3;
    }

    __syncthreads();
    float* fs = (float*)sm;   // 128 x 113 fp32
#pragma unroll
    for (int mt = 0; mt < 2; mt++) {
#pragma unroll
        for (int nt = 0; nt < 7; nt++) {
            int r = warp_m * 32 + mt * 16 + rw;
            int c = warp_n * 56 + nt * 8 + q * 2;
            float b0 = bias[colBase + c], b1 = bias[colBase + c + 1];
            fs[r * 113 + c]           = acc[mt][nt][0] + b0;
            fs[r * 113 + c + 1]       = acc[mt][nt][1] + b1;
            fs[(r + 8) * 113 + c]     = acc[mt][nt][2] + b0;
            fs[(r + 8) * 113 + c + 1] = acc[mt][nt][3] + b1;
        }
    }
    __syncthreads();

    const int d2l = tid & 7;
    const int d2g = bx * 8 + d2l;
#pragma unroll
    for (int i = 0; i < 4; i++) {
        int p = tid + 256 * i;
        int r = p >> 3;
        int n = rowBase + r;
        float raw[14];
#pragma unroll
        for (int j = 0; j < 14; j++) raw[j] = fs[r * 113 + d2l * 14 + j];
        float t = x[(size_t)n * 256 + xoff + d2g];
        float ld;
        float outv = spline_eval(raw, t, &ld);

        z[(size_t)n * 256 + zoff + d2g] = outv;

        if (zb != nullptr) {
            float nbv = __shfl_down_sync(0xffffffffu, outv, 1);
            if ((d2l & 1) == 0) {
                uint32_t bbv, ssv;
                split2h(outv, nbv, bbv, ssv);
                zb[n * 64 + gidx(d2g >> 1)] = bbv;
                zs[n * 64 + gidx(d2g >> 1)] = ssv;
            }
        }

        float v = ld;
#pragma unroll
        for (int o = 4; o > 0; o >>= 1) v += __shfl_xor_sync(0xffffffffu, v, o);
        if (d2l == 0) ldpart[(size_t)n * 16 + bx] = v;
    }
#undef STAGE2
}

// ======================= final logdet reduce =======================
__global__ void __launch_bounds__(256) reduce_ld(
    const float* __restrict__ p1, const float* __restrict__ p2,
    float* __restrict__ logdet)
{
    int n = blockIdx.x * 256 + threadIdx.x;
    const float4* a = (const float4*)(p1 + (size_t)n * 16);
    const float4* b = (const float4*)(p2 + (size_t)n * 16);
    float s = 0.f;
#pragma unroll
    for (int i = 0; i < 4; i++) {
        float4 u = a[i];
        s += u.x + u.y + u.z + u.w;
    }
#pragma unroll
    for (int i = 0; i < 4; i++) {
        float4 u = b[i];
        s += u.x + u.y + u.z + u.w;
    }
    logdet[n] = s;
}

// ======================= host side =======================
extern "C" void kernel_launch(void* const* d_in, const int* in_sizes, int n_in,
                              void* d_out, int out_size)
{
    const float* x     = (const float*)d_in[0];
    const float* f0_w0 = (const float*)d_in[1];
    const float* f0_b0 = (const float*)d_in[2];
    const float* f0_w1 = (const float*)d_in[3];
    const float* f0_b1 = (const float*)d_in[4];
    const float* f1_w0 = (const float*)d_in[5];
    const float* f1_b0 = (const float*)d_in[6];
    const float* f1_w1 = (const float*)d_in[7];
    const float* f1_b1 = (const float*)d_in[8];

    const int N = in_sizes[0] / 256;              // 32768
    float* z      = (float*)d_out;
    float* logdet = z + (size_t)N * 256;

    uint32_t *xsb, *xss, *hb, *hs, *w0b, *w0s, *w1b, *w1s;
    float* ldp;
    cudaGetSymbolAddress((void**)&xsb, g_xs_big);
    cudaGetSymbolAddress((void**)&xss, g_xs_sml);
    cudaGetSymbolAddress((void**)&hb,  g_h_big);
    cudaGetSymbolAddress((void**)&hs,  g_h_sml);
    cudaGetSymbolAddress((void**)&w0b, g_w0b);
    cudaGetSymbolAddress((void**)&w0s, g_w0s);
    cudaGetSymbolAddress((void**)&w1b, g_w1b);
    cudaGetSymbolAddress((void**)&w1s, g_w1s);
    cudaGetSymbolAddress((void**)&ldp, g_ldp);
    float* ldp1 = ldp;
    float* ldp2 = ldp + (size_t)N * 16;

    cudaFuncSetAttribute((const void*)gemm1_h3,    cudaFuncAttributeMaxDynamicSharedMemorySize, G1_SMEM);
    cudaFuncSetAttribute((const void*)gemm2_fused, cudaFuncAttributeMaxDynamicSharedMemorySize, G2_SMEM);

    const dim3 g1(512 / 64, N / 128);     // (8, 256) -> ~7 waves
    const dim3 g2f(16, N / 128);          // (16, 256)
    const int nConvBlocks = N * 64 / 256; // 8192

    // ---- coupling 1 ----
    conv_all<<<960 + nConvBlocks, 256>>>(x, 0, f0_w0, f0_w1, f1_w0, f1_w1,
                                         w0b, w0s, w1b, w1s, xsb, xss);           // 1
    gemm1_h3<<<g1, 256, G1_SMEM>>>(xsb, xss, w0b, w0s, f0_b0, hb, hs, 512, 64);   // 2
    gemm2_fused<<<g2f, 256, G2_SMEM>>>(hb, hs, w1b, f0_b1,
                                       x, 128, z, 128, xsb, xss, ldp1);           // 3

    // ---- coupling 2 ----
    gemm1_h3<<<g1, 256, G1_SMEM>>>(xsb, xss, w0b + 512 * 64, w0s + 512 * 64,
                                   f1_b0, hb, hs, 512, 64);                       // 4
    gemm2_fused<<<g2f, 256, G2_SMEM>>>(hb, hs, w1b + 1792 * 256, f1_b1,
                                       x, 0, z, 0, nullptr, nullptr, ldp2);       // 5
    reduce_ld<<<N / 256, 256>>>(ldp1, ldp2, logdet);                              // 6
}